// round 2
// baseline (speedup 1.0000x reference)
#include <cuda_runtime.h>

// ESH sampler: B rows, D=64, n_steps leapfrog-like steps of 2 half-steps.
// Layout: 4 lanes per row (group), 8 rows per warp, 16 elems (4 float4) per lane.
// Ownership: lane-in-group p owns float4 chunks {p, p+4, p+8, p+12} of the 16
// float4s in a 64-float row -> coalesced 64B-per-row stores per unrolled j.

__device__ __forceinline__ float grp_sum4(float v) {
    v += __shfl_xor_sync(0xffffffffu, v, 1);
    v += __shfl_xor_sync(0xffffffffu, v, 2);
    return v;
}

__device__ __forceinline__ void half_step(
    const float4 (&xv)[4], float4 (&uv)[4], const float4 (&pv)[4],
    float& r, float ed)
{
    // grad = prec * x ; partial sums
    float4 g[4];
    float gsq = 0.0f, ug = 0.0f;
#pragma unroll
    for (int j = 0; j < 4; j++) {
        g[j].x = pv[j].x * xv[j].x;
        g[j].y = pv[j].y * xv[j].y;
        g[j].z = pv[j].z * xv[j].z;
        g[j].w = pv[j].w * xv[j].w;
        gsq = fmaf(g[j].x, g[j].x, gsq); ug = fmaf(uv[j].x, g[j].x, ug);
        gsq = fmaf(g[j].y, g[j].y, gsq); ug = fmaf(uv[j].y, g[j].y, ug);
        gsq = fmaf(g[j].z, g[j].z, gsq); ug = fmaf(uv[j].z, g[j].z, ug);
        gsq = fmaf(g[j].w, g[j].w, gsq); ug = fmaf(uv[j].w, g[j].w, ug);
    }
    gsq = grp_sum4(gsq);
    ug  = grp_sum4(ug);

    float gn0    = fmaxf(sqrtf(gsq), 1e-10f);
    float g_norm = fminf(gn0, 10.0f);
    float inv    = 1.0f / gn0;            // grad_e = grad * inv
    float ude    = -ug * inv;             // u_dot_e
    float t      = expf(-ed * g_norm);    // exp(-e*g/d)
    float A2     = (ude - 1.0f) * (t * t);
    float opu    = 1.0f + ude;
    float A      = opu + A2;
    float Bc     = 2.0f * t;
    bool  cond   = ude > -0.999f;

    float nsq = 0.0f;
#pragma unroll
    for (int j = 0; j < 4; j++) {
        float ge, perp, un;
        ge = g[j].x * inv; perp = fmaf(ge, ude, uv[j].x);
        un = cond ? fmaf(-A, ge, Bc * perp) : ge;
        uv[j].x = un; nsq = fmaf(un, un, nsq);

        ge = g[j].y * inv; perp = fmaf(ge, ude, uv[j].y);
        un = cond ? fmaf(-A, ge, Bc * perp) : ge;
        uv[j].y = un; nsq = fmaf(un, un, nsq);

        ge = g[j].z * inv; perp = fmaf(ge, ude, uv[j].z);
        un = cond ? fmaf(-A, ge, Bc * perp) : ge;
        uv[j].z = un; nsq = fmaf(un, un, nsq);

        ge = g[j].w * inv; perp = fmaf(ge, ude, uv[j].w);
        un = cond ? fmaf(-A, ge, Bc * perp) : ge;
        uv[j].w = un; nsq = fmaf(un, un, nsq);
    }
    nsq = grp_sum4(nsq);
    float invn = 1.0f / fmaxf(sqrtf(nsq), 1e-10f);
#pragma unroll
    for (int j = 0; j < 4; j++) {
        uv[j].x *= invn; uv[j].y *= invn; uv[j].z *= invn; uv[j].w *= invn;
    }

    float Z  = opu - A2;
    float lg = logf(0.5f * fmaxf(Z, 1e-10f));
    float dr = cond ? fmaf(ed, g_norm, lg) : (-ed * g_norm);
    r += dr;
}

__global__ __launch_bounds__(256)
void esh_kernel(const float* __restrict__ x0,
                const float* __restrict__ u0,
                const float* __restrict__ prec,
                const float* __restrict__ eps_p,
                const int* __restrict__ nsteps_p,
                float* __restrict__ out,
                int B)
{
    const int tid  = threadIdx.x;
    const int lane = tid & 31;
    const int p    = lane & 3;       // lane within group
    const int grp  = lane >> 2;      // 0..7 : row within warp
    const int warp = tid >> 5;       // 0..7
    const int row  = blockIdx.x * 64 + warp * 8 + grp;
    if (row >= B) return;

    const float eps = *eps_p;
    const int n_steps = *nsteps_p;
    const float ed = (0.5f * eps) * (1.0f / 64.0f);  // e/d, e = eps/2

    float4 xv[4], uv[4], pv[4];
    {
        const float4* xp = reinterpret_cast<const float4*>(x0 + (size_t)row * 64);
        const float4* up = reinterpret_cast<const float4*>(u0 + (size_t)row * 64);
        const float4* pp = reinterpret_cast<const float4*>(prec);
#pragma unroll
        for (int j = 0; j < 4; j++) {
            xv[j] = xp[p + 4 * j];
            uv[j] = up[p + 4 * j];
            pv[j] = pp[p + 4 * j];
        }
    }
    float r = 0.0f;

    const size_t rowstride = (size_t)B * 64;
    const size_t XN = (size_t)(n_steps + 1) * rowstride;
    float* outr = out + 2 * XN + row;

    // step 0: x0, u0, r0=0
    float4* ox = reinterpret_cast<float4*>(out + (size_t)row * 64);
    float4* ou = reinterpret_cast<float4*>(out + XN + (size_t)row * 64);
#pragma unroll
    for (int j = 0; j < 4; j++) { ox[p + 4 * j] = xv[j]; ou[p + 4 * j] = uv[j]; }
    if (p == 0) *outr = 0.0f;

    const size_t f4stride = rowstride / 4;  // float4 elements per step

    for (int s = 1; s <= n_steps; s++) {
        half_step(xv, uv, pv, r, ed);
#pragma unroll
        for (int j = 0; j < 4; j++) {
            xv[j].x = fmaf(eps, uv[j].x, xv[j].x);
            xv[j].y = fmaf(eps, uv[j].y, xv[j].y);
            xv[j].z = fmaf(eps, uv[j].z, xv[j].z);
            xv[j].w = fmaf(eps, uv[j].w, xv[j].w);
        }
        half_step(xv, uv, pv, r, ed);

        ox += f4stride;
        ou += f4stride;
        outr += B;
#pragma unroll
        for (int j = 0; j < 4; j++) { ox[p + 4 * j] = xv[j]; ou[p + 4 * j] = uv[j]; }
        if (p == 0) *outr = r;
    }
}

extern "C" void kernel_launch(void* const* d_in, const int* in_sizes, int n_in,
                              void* d_out, int out_size)
{
    const float* x0     = (const float*)d_in[0];
    const float* u0     = (const float*)d_in[1];
    const float* prec   = (const float*)d_in[2];
    const float* eps_p  = (const float*)d_in[3];
    const int*   nsteps = (const int*)d_in[4];
    float* out = (float*)d_out;

    int B = in_sizes[0] / 64;
    int rows_per_block = 64;  // 256 threads, 8 warps, 8 rows/warp
    int grid = (B + rows_per_block - 1) / rows_per_block;
    esh_kernel<<<grid, 256>>>(x0, u0, prec, eps_p, nsteps, out, B);
}

// round 3
// speedup vs baseline: 1.2138x; 1.2138x over previous
#include <cuda_runtime.h>

// ESH sampler: B rows, D=64, n_steps of 2 half-steps each.
// Layout: 8 lanes per row (group), 4 rows per warp, 8 elems (2 float4) per lane.
// Lane-in-group p owns float4 chunks {p, p+8} -> stores at unroll step j are
// float4s {8j..8j+7} = 128B contiguous per row, 512B coalesced per warp.
//
// Algebra: u_new = Bc*u + ((Bc*ude - A)/||g||)*g  (== reference form), with the
// cond=false branch folded via Bs=0, Cc=1/||g||. u carried unnormalized with a
// scalar scale `us` (normalize folded into scalar coefficients); materialized
// only at store time.

__device__ __forceinline__ float grp_sum8(float v) {
    v += __shfl_xor_sync(0xffffffffu, v, 1);
    v += __shfl_xor_sync(0xffffffffu, v, 2);
    v += __shfl_xor_sync(0xffffffffu, v, 4);
    return v;
}

__device__ __forceinline__ void half_step(
    const float4 (&xv)[2], float4 (&uv)[2], const float4 (&pv)[2],
    float& us, float& r, float ed)
{
    // grad = prec * x ; partial sums of ||g||^2 and u_raw . g
    float4 g[2];
    float gsq = 0.0f, ugr = 0.0f;
#pragma unroll
    for (int j = 0; j < 2; j++) {
        g[j].x = pv[j].x * xv[j].x; gsq = fmaf(g[j].x, g[j].x, gsq); ugr = fmaf(uv[j].x, g[j].x, ugr);
        g[j].y = pv[j].y * xv[j].y; gsq = fmaf(g[j].y, g[j].y, gsq); ugr = fmaf(uv[j].y, g[j].y, ugr);
        g[j].z = pv[j].z * xv[j].z; gsq = fmaf(g[j].z, g[j].z, gsq); ugr = fmaf(uv[j].z, g[j].z, ugr);
        g[j].w = pv[j].w * xv[j].w; gsq = fmaf(g[j].w, g[j].w, gsq); ugr = fmaf(uv[j].w, g[j].w, ugr);
    }
    gsq = grp_sum8(gsq);
    ugr = grp_sum8(ugr);

    float rs     = rsqrtf(fmaxf(gsq, 1e-20f));   // == 1/gn0
    float g_norm = fminf(gsq * rs, 10.0f);
    float ude    = -(us * ugr) * rs;             // u_true . grad_e
    float t      = __expf(-ed * g_norm);         // exp(-e*g/d)
    float A2     = (ude - 1.0f) * (t * t);
    float opu    = 1.0f + ude;
    float A      = opu + A2;
    bool  cond   = ude > -0.999f;
    float Bc     = 2.0f * t;
    float Bs     = cond ? Bc * us : 0.0f;                  // coeff on u_raw
    float Cc     = cond ? fmaf(Bc, ude, -A) * rs : rs;     // coeff on g

    float nsq = 0.0f;
#pragma unroll
    for (int j = 0; j < 2; j++) {
        float un;
        un = fmaf(Cc, g[j].x, Bs * uv[j].x); uv[j].x = un; nsq = fmaf(un, un, nsq);
        un = fmaf(Cc, g[j].y, Bs * uv[j].y); uv[j].y = un; nsq = fmaf(un, un, nsq);
        un = fmaf(Cc, g[j].z, Bs * uv[j].z); uv[j].z = un; nsq = fmaf(un, un, nsq);
        un = fmaf(Cc, g[j].w, Bs * uv[j].w); uv[j].w = un; nsq = fmaf(un, un, nsq);
    }
    nsq = grp_sum8(nsq);
    us  = rsqrtf(fmaxf(nsq, 1e-20f));            // new scale: u_true = us * u_raw

    float Z  = opu - A2;
    float dr = cond ? fmaf(ed, g_norm, __logf(0.5f * fmaxf(Z, 1e-10f)))
                    : -ed * g_norm;
    r += dr;
}

__global__ __launch_bounds__(256, 4)
void esh_kernel(const float* __restrict__ x0,
                const float* __restrict__ u0,
                const float* __restrict__ prec,
                const float* __restrict__ eps_p,
                const int* __restrict__ nsteps_p,
                float* __restrict__ out,
                int B)
{
    const int tid  = threadIdx.x;
    const int lane = tid & 31;
    const int p    = lane & 7;       // lane within group (8 per row)
    const int grp  = lane >> 3;      // 0..3 : row within warp
    const int warp = tid >> 5;       // 0..7
    const int row  = blockIdx.x * 32 + warp * 4 + grp;
    if (row >= B) return;

    const float eps = *eps_p;
    const int n_steps = *nsteps_p;
    const float ed = (0.5f * eps) * (1.0f / 64.0f);  // e/d, e = eps/2

    float4 xv[2], uv[2], pv[2];
    {
        const float4* xp = reinterpret_cast<const float4*>(x0 + (size_t)row * 64);
        const float4* up = reinterpret_cast<const float4*>(u0 + (size_t)row * 64);
        const float4* pp = reinterpret_cast<const float4*>(prec);
#pragma unroll
        for (int j = 0; j < 2; j++) {
            xv[j] = xp[p + 8 * j];
            uv[j] = up[p + 8 * j];
            pv[j] = pp[p + 8 * j];
        }
    }
    float r = 0.0f;
    float us = 1.0f;   // u_true = us * uv

    const size_t rowstride = (size_t)B * 64;
    const size_t XN = (size_t)(n_steps + 1) * rowstride;
    float* outr = out + 2 * XN + row;

    // step 0: x0, u0, r0=0
    float4* ox = reinterpret_cast<float4*>(out + (size_t)row * 64);
    float4* ou = reinterpret_cast<float4*>(out + XN + (size_t)row * 64);
#pragma unroll
    for (int j = 0; j < 2; j++) {
        __stcs(&ox[p + 8 * j], xv[j]);
        __stcs(&ou[p + 8 * j], uv[j]);
    }
    if (p == 0) __stcs(outr, 0.0f);

    const size_t f4stride = rowstride / 4;  // float4 elements per step

    for (int s = 1; s <= n_steps; s++) {
        half_step(xv, uv, pv, us, r, ed);
        // x += eps * u_true  (fold us into the coefficient)
        {
            const float c = eps * us;
#pragma unroll
            for (int j = 0; j < 2; j++) {
                xv[j].x = fmaf(c, uv[j].x, xv[j].x);
                xv[j].y = fmaf(c, uv[j].y, xv[j].y);
                xv[j].z = fmaf(c, uv[j].z, xv[j].z);
                xv[j].w = fmaf(c, uv[j].w, xv[j].w);
            }
        }
        half_step(xv, uv, pv, us, r, ed);

        ox += f4stride;
        ou += f4stride;
        outr += B;
        // materialize normalized u and store x, u
#pragma unroll
        for (int j = 0; j < 2; j++) {
            float4 w;
            w.x = us * uv[j].x; w.y = us * uv[j].y;
            w.z = us * uv[j].z; w.w = us * uv[j].w;
            uv[j] = w;
            __stcs(&ox[p + 8 * j], xv[j]);
            __stcs(&ou[p + 8 * j], w);
        }
        us = 1.0f;
        if (p == 0) __stcs(outr, r);
    }
}

extern "C" void kernel_launch(void* const* d_in, const int* in_sizes, int n_in,
                              void* d_out, int out_size)
{
    const float* x0     = (const float*)d_in[0];
    const float* u0     = (const float*)d_in[1];
    const float* prec   = (const float*)d_in[2];
    const float* eps_p  = (const float*)d_in[3];
    const int*   nsteps = (const int*)d_in[4];
    float* out = (float*)d_out;

    int B = in_sizes[0] / 64;
    int rows_per_block = 32;  // 256 threads, 8 warps, 4 rows/warp
    int grid = (B + rows_per_block - 1) / rows_per_block;
    esh_kernel<<<grid, 256>>>(x0, u0, prec, eps_p, nsteps, out, B);
}